// round 2
// baseline (speedup 1.0000x reference)
#include <cuda_runtime.h>
#include <math.h>

#define GN   8192
#define FIN  256
#define FOUT 64
#define NEG  0.01f

// ---------------- device scratch (no allocations allowed) ----------------
__device__ __align__(16) float g_Wh[GN * FOUT];
__device__ __align__(16) float g_t[GN];     // s_tar
__device__ __align__(16) float g_th[GN];    // threshold  -(s_src + a_b)
__device__ __align__(16) float g_P[GN];     // exp(s_src + a_b)
__device__ __align__(16) float g_p[GN];     // exp(0.01*(s_src + a_b))
__device__ __align__(16) float g_E[GN];     // exp(t)
__device__ __align__(16) float g_e[GN];     // exp(0.01*t)
__device__ __align__(16) int   g_pos[GN];   // sorted-position -> original index
__device__ __align__(16) int   g_k[GN];     // lower_bound(t_sorted, th_i)
__device__ __align__(16) float g_chunkLo[64 * 64];
__device__ __align__(16) float g_chunkHi[64 * 64];
__device__ __align__(16) float g_offLo[64 * 64];
__device__ __align__(16) float g_offHiS[65 * 64];
__device__ __align__(16) float g_PreLo[(GN + 1) * FOUT];
__device__ __align__(16) float g_SufHi[(GN + 1) * FOUT];
__device__ __align__(16) float g_denom[GN];

// ---------------- K1: Wh = H @ W + bW  (64x64 tile, BK=32) ----------------
__global__ __launch_bounds__(256) void k1_gemm(const float* __restrict__ H,
                                               const float* __restrict__ W,
                                               const float* __restrict__ bW) {
    __shared__ float Hs[32][64];  // [k][row]
    __shared__ float Ws[32][64];  // [k][col]
    int tid = threadIdx.x;
    int row0 = blockIdx.x * 64;
    int tx = tid & 15, ty = tid >> 4;
    float acc[4][4] = {};
    for (int k0 = 0; k0 < FIN; k0 += 32) {
#pragma unroll
        for (int i = 0; i < 2; i++) {
            int idx = tid + i * 256;       // 0..511
            int r = idx >> 3;              // 0..63
            int kq = idx & 7;              // 0..7
            float4 v = *(const float4*)(H + (size_t)(row0 + r) * FIN + k0 + kq * 4);
            Hs[kq * 4 + 0][r] = v.x;
            Hs[kq * 4 + 1][r] = v.y;
            Hs[kq * 4 + 2][r] = v.z;
            Hs[kq * 4 + 3][r] = v.w;
        }
#pragma unroll
        for (int i = 0; i < 2; i++) {
            int idx = tid + i * 256;
            int kk = idx >> 4;             // 0..31
            int cq = idx & 15;             // 0..15
            *(float4*)&Ws[kk][cq * 4] =
                *(const float4*)(W + (size_t)(k0 + kk) * FOUT + cq * 4);
        }
        __syncthreads();
#pragma unroll
        for (int kk = 0; kk < 32; kk++) {
            float4 a = *(float4*)&Hs[kk][ty * 4];
            float4 b = *(float4*)&Ws[kk][tx * 4];
            acc[0][0] += a.x * b.x; acc[0][1] += a.x * b.y; acc[0][2] += a.x * b.z; acc[0][3] += a.x * b.w;
            acc[1][0] += a.y * b.x; acc[1][1] += a.y * b.y; acc[1][2] += a.y * b.z; acc[1][3] += a.y * b.w;
            acc[2][0] += a.z * b.x; acc[2][1] += a.z * b.y; acc[2][2] += a.z * b.z; acc[2][3] += a.z * b.w;
            acc[3][0] += a.w * b.x; acc[3][1] += a.w * b.y; acc[3][2] += a.w * b.z; acc[3][3] += a.w * b.w;
        }
        __syncthreads();
    }
    float4 bv = *(const float4*)(bW + tx * 4);
#pragma unroll
    for (int u = 0; u < 4; u++) {
        float4 o;
        o.x = acc[u][0] + bv.x;
        o.y = acc[u][1] + bv.y;
        o.z = acc[u][2] + bv.z;
        o.w = acc[u][3] + bv.w;
        *(float4*)&g_Wh[(size_t)(row0 + ty * 4 + u) * FOUT + tx * 4] = o;
    }
}

// ---------------- K2: per-node scalars (one warp per row) ----------------
__global__ __launch_bounds__(256) void k2_scalars(const float* __restrict__ aw,
                                                  const float* __restrict__ ab) {
    int tid = threadIdx.x;
    int lane = tid & 31, w = tid >> 5;
    int row = blockIdx.x * 8 + w;
    const float* wh = g_Wh + (size_t)row * FOUT;
    float xl = wh[lane], xh = wh[lane + 32];
    float ssrc = xl * aw[lane] + xh * aw[lane + 32];
    float star = xl * aw[FOUT + lane] + xh * aw[FOUT + lane + 32];
#pragma unroll
    for (int o = 16; o; o >>= 1) {
        ssrc += __shfl_xor_sync(0xffffffffu, ssrc, o);
        star += __shfl_xor_sync(0xffffffffu, star, o);
    }
    if (lane == 0) {
        float sb = ssrc + ab[0];
        g_t[row] = star;
        g_th[row] = -sb;
        g_P[row] = expf(sb);
        g_p[row] = expf(NEG * sb);
        g_E[row] = expf(star);
        g_e[row] = expf(NEG * star);
    }
}

// ------- K3: rank-by-counting (mode 0) / lower_bound count (mode 1) -------
__global__ __launch_bounds__(256) void k3_count(int mode) {
    __shared__ __align__(16) float st[GN];
    int tid = threadIdx.x;
    for (int i = tid; i < GN / 4; i += 256)
        ((float4*)st)[i] = ((const float4*)g_t)[i];
    __syncthreads();
    int lane = tid & 31, w = tid >> 5;
    int idx = blockIdx.x * 8 + w;
    float qv = (mode == 0) ? g_t[idx] : g_th[idx];
    int cnt = 0;
#pragma unroll 4
    for (int i = 0; i < 64; i++) {
        int m4 = i * 32 + lane;
        float4 v = ((float4*)st)[m4];
        if (mode == 0) {
            int m = m4 * 4;
            cnt += (v.x < qv) || (v.x == qv && (m + 0) < idx);
            cnt += (v.y < qv) || (v.y == qv && (m + 1) < idx);
            cnt += (v.z < qv) || (v.z == qv && (m + 2) < idx);
            cnt += (v.w < qv) || (v.w == qv && (m + 3) < idx);
        } else {
            cnt += (v.x < qv) + (v.y < qv) + (v.z < qv) + (v.w < qv);
        }
    }
#pragma unroll
    for (int o = 16; o; o >>= 1) cnt += __shfl_xor_sync(0xffffffffu, cnt, o);
    if (lane == 0) {
        if (mode == 0) g_pos[cnt] = idx;   // ranks are a permutation (tie-broken)
        else           g_k[idx] = cnt;
    }
}

// ---------------- K4: per-chunk weighted partial sums ----------------
__global__ __launch_bounds__(64) void k4_chunks() {
    int c = blockIdx.x, f = threadIdx.x;
    __shared__ int   sj[128];
    __shared__ float swl[128], swh[128];
    for (int r = f; r < 128; r += 64) {
        int jj = g_pos[c * 128 + r];
        sj[r] = jj; swl[r] = g_e[jj]; swh[r] = g_E[jj];
    }
    __syncthreads();
    float accLo = 0.f, accHi = 0.f;
#pragma unroll 8
    for (int r = 0; r < 128; r++) {
        float x = g_Wh[(size_t)sj[r] * FOUT + f];
        accLo += swl[r] * x;
        accHi += swh[r] * x;
    }
    g_chunkLo[c * 64 + f] = accLo;
    g_chunkHi[c * 64 + f] = accHi;
}

// ---------------- K5: chunk-level scan offsets ----------------
__global__ __launch_bounds__(64) void k5_offsets() {
    int f = threadIdx.x;
    float run = 0.f;
    for (int c = 0; c < 64; c++) {
        g_offLo[c * 64 + f] = run;
        run += g_chunkLo[c * 64 + f];
    }
    float run2 = 0.f;
    g_offHiS[64 * 64 + f] = 0.f;
    for (int c = 63; c >= 0; c--) {
        run2 += g_chunkHi[c * 64 + f];
        g_offHiS[c * 64 + f] = run2;
    }
}

// ---------------- K6: fill PreLo (forward) / SufHi (backward) ----------------
__global__ __launch_bounds__(64) void k6_fill() {
    int c = blockIdx.x, f = threadIdx.x;
    __shared__ int   sj[128];
    __shared__ float swl[128], swh[128];
    for (int r = f; r < 128; r += 64) {
        int jj = g_pos[c * 128 + r];
        sj[r] = jj; swl[r] = g_e[jj]; swh[r] = g_E[jj];
    }
    __syncthreads();
    int base = c * 128;
    float run = g_offLo[c * 64 + f];
    for (int r0 = 0; r0 < 128; r0 += 8) {
        float x[8];
#pragma unroll
        for (int u = 0; u < 8; u++) x[u] = g_Wh[(size_t)sj[r0 + u] * FOUT + f];
#pragma unroll
        for (int u = 0; u < 8; u++) {
            g_PreLo[(size_t)(base + r0 + u) * FOUT + f] = run;
            run += swl[r0 + u] * x[u];
        }
    }
    if (c == 63) g_PreLo[(size_t)GN * FOUT + f] = run;
    float run2 = g_offHiS[(c + 1) * 64 + f];
    if (c == 63) g_SufHi[(size_t)GN * FOUT + f] = 0.f;
    for (int r0 = 120; r0 >= 0; r0 -= 8) {
        float x[8];
#pragma unroll
        for (int u = 0; u < 8; u++) x[u] = g_Wh[(size_t)sj[r0 + u] * FOUT + f];
#pragma unroll
        for (int u = 7; u >= 0; u--) {
            run2 += swh[r0 + u] * x[u];
            g_SufHi[(size_t)(base + r0 + u) * FOUT + f] = run2;
        }
    }
}

// ---------------- K7: denominator (streams A: 268 MB, DRAM-bound) ----------------
__global__ __launch_bounds__(256) void k7_denom(const int* __restrict__ A) {
    int ib = blockIdx.x * 16;
    int tid = threadIdx.x;
    float th[16];
    float acc1[16] = {}, acc2[16] = {};
#pragma unroll
    for (int r = 0; r < 16; r++) th[r] = g_th[ib + r];
#pragma unroll 1
    for (int it = 0; it < 8; it++) {
        int jq = it * 256 + tid;                     // quad index: cols 4*jq..4*jq+3
        float4 Ev = ((const float4*)g_E)[jq];
        float4 ev = ((const float4*)g_e)[jq];
        float4 tv = ((const float4*)g_t)[jq];
#pragma unroll
        for (int r = 0; r < 16; r++) {
            int4 a = ((const int4*)A)[(size_t)(ib + r) * (GN / 4) + jq];
            if (a.x) { if (tv.x >= th[r]) acc1[r] += Ev.x; else acc2[r] += ev.x; }
            if (a.y) { if (tv.y >= th[r]) acc1[r] += Ev.y; else acc2[r] += ev.y; }
            if (a.z) { if (tv.z >= th[r]) acc1[r] += Ev.z; else acc2[r] += ev.z; }
            if (a.w) { if (tv.w >= th[r]) acc1[r] += Ev.w; else acc2[r] += ev.w; }
        }
    }
    __shared__ float s1[16][8], s2[16][8];
    int lane = tid & 31, w = tid >> 5;
#pragma unroll
    for (int r = 0; r < 16; r++) {
        float v1 = acc1[r], v2 = acc2[r];
#pragma unroll
        for (int o = 16; o; o >>= 1) {
            v1 += __shfl_xor_sync(0xffffffffu, v1, o);
            v2 += __shfl_xor_sync(0xffffffffu, v2, o);
        }
        if (lane == 0) { s1[r][w] = v1; s2[r][w] = v2; }
    }
    __syncthreads();
    if (tid < 16) {
        float d1 = 0.f, d2 = 0.f;
#pragma unroll
        for (int q = 0; q < 8; q++) { d1 += s1[tid][q]; d2 += s2[tid][q]; }
        int i = ib + tid;
        g_denom[i] = g_P[i] * d1 + g_p[i] * d2;
    }
}

// ---------------- K8: gather + sigmoid ----------------
__global__ __launch_bounds__(256) void k8_out(float* __restrict__ out) {
    int gid = blockIdx.x * 256 + threadIdx.x;
    int i = gid >> 6, f = gid & 63;
    int k = g_k[i];
    float num = g_P[i] * g_SufHi[(size_t)k * FOUT + f] +
                g_p[i] * g_PreLo[(size_t)k * FOUT + f];
    float z = num / g_denom[i];
    out[gid] = 1.0f / (1.0f + __expf(-z));
}

// ---------------- launch ----------------
extern "C" void kernel_launch(void* const* d_in, const int* in_sizes, int n_in,
                              void* d_out, int out_size) {
    const float* H  = (const float*)d_in[0];
    const int*   A  = (const int*)d_in[1];
    const float* W  = (const float*)d_in[2];
    const float* bW = (const float*)d_in[3];
    const float* aw = (const float*)d_in[4];
    const float* ab = (const float*)d_in[5];
    float* out = (float*)d_out;

    k1_gemm<<<GN / 64, 256>>>(H, W, bW);
    k2_scalars<<<GN / 8, 256>>>(aw, ab);
    k3_count<<<GN / 8, 256>>>(0);   // ranks -> g_pos
    k3_count<<<GN / 8, 256>>>(1);   // lower-bound counts -> g_k
    k4_chunks<<<64, 64>>>();
    k5_offsets<<<1, 64>>>();
    k6_fill<<<64, 64>>>();
    k7_denom<<<GN / 16, 256>>>(A);
    k8_out<<<(GN * FOUT) / 256, 256>>>(out);
}

// round 3
// speedup vs baseline: 1.1260x; 1.1260x over previous
#include <cuda_runtime.h>
#include <math.h>

#define GN     8192
#define FIN    256
#define FOUT   64
#define NEG    0.01f
#define SBLK   512      // streaming (denominator) blocks in fused kernel
#define RBLK   128      // ranking blocks in fused kernel
#define NCHUNK 128      // sorted-order chunks
#define CSZ    64       // elements per chunk

// ---------------- device scratch (no allocations allowed) ----------------
__device__ __align__(16) float g_Wh[GN * FOUT];
__device__ __align__(16) float g_t[GN];     // s_tar
__device__ __align__(16) float g_th[GN];    // threshold  -(s_src + a_b)
__device__ __align__(16) float g_P[GN];     // exp(s_src + a_b)
__device__ __align__(16) float g_p[GN];     // exp(0.01*(s_src + a_b))
__device__ __align__(16) float g_E[GN];     // exp(t)
__device__ __align__(16) float g_e[GN];     // exp(0.01*t)
__device__ __align__(16) int   g_pos[GN];   // sorted-position -> original index
__device__ __align__(16) int   g_k[GN];     // lower_bound(t_sorted, th_i)
__device__ __align__(16) float g_chunkLo[NCHUNK * FOUT];
__device__ __align__(16) float g_chunkHi[NCHUNK * FOUT];
__device__ __align__(16) float g_PreLo[(GN + 1) * FOUT];
__device__ __align__(16) float g_SufHi[(GN + 1) * FOUT];
__device__ __align__(16) float g_denom[GN];

// ---------------- K1: Wh = H @ W + bW  + per-row scalar epilogue ----------------
__global__ __launch_bounds__(256) void k1_gemm_scal(const float* __restrict__ H,
                                                    const float* __restrict__ W,
                                                    const float* __restrict__ bW,
                                                    const float* __restrict__ aw,
                                                    const float* __restrict__ ab) {
    __shared__ float Hs[32][64];  // [k][row]
    __shared__ float Ws[32][64];  // [k][col]
    int tid = threadIdx.x;
    int row0 = blockIdx.x * 64;
    int tx = tid & 15, ty = tid >> 4;
    float acc[4][4] = {};
    for (int k0 = 0; k0 < FIN; k0 += 32) {
#pragma unroll
        for (int i = 0; i < 2; i++) {
            int idx = tid + i * 256;       // 0..511
            int r = idx >> 3;              // 0..63
            int kq = idx & 7;              // 0..7
            float4 v = *(const float4*)(H + (size_t)(row0 + r) * FIN + k0 + kq * 4);
            Hs[kq * 4 + 0][r] = v.x;
            Hs[kq * 4 + 1][r] = v.y;
            Hs[kq * 4 + 2][r] = v.z;
            Hs[kq * 4 + 3][r] = v.w;
        }
#pragma unroll
        for (int i = 0; i < 2; i++) {
            int idx = tid + i * 256;
            int kk = idx >> 4;             // 0..31
            int cq = idx & 15;             // 0..15
            *(float4*)&Ws[kk][cq * 4] =
                *(const float4*)(W + (size_t)(k0 + kk) * FOUT + cq * 4);
        }
        __syncthreads();
#pragma unroll
        for (int kk = 0; kk < 32; kk++) {
            float4 a = *(float4*)&Hs[kk][ty * 4];
            float4 b = *(float4*)&Ws[kk][tx * 4];
            acc[0][0] += a.x * b.x; acc[0][1] += a.x * b.y; acc[0][2] += a.x * b.z; acc[0][3] += a.x * b.w;
            acc[1][0] += a.y * b.x; acc[1][1] += a.y * b.y; acc[1][2] += a.y * b.z; acc[1][3] += a.y * b.w;
            acc[2][0] += a.z * b.x; acc[2][1] += a.z * b.y; acc[2][2] += a.z * b.z; acc[2][3] += a.z * b.w;
            acc[3][0] += a.w * b.x; acc[3][1] += a.w * b.y; acc[3][2] += a.w * b.z; acc[3][3] += a.w * b.w;
        }
        __syncthreads();
    }
    float4 bv = *(const float4*)(bW + tx * 4);
    // per-column attention weights for this thread's 4 columns
    float4 a1 = *(const float4*)(aw + tx * 4);
    float4 a2 = *(const float4*)(aw + FOUT + tx * 4);
    float ps[4], pt2[4];
#pragma unroll
    for (int u = 0; u < 4; u++) {
        float4 o;
        o.x = acc[u][0] + bv.x;
        o.y = acc[u][1] + bv.y;
        o.z = acc[u][2] + bv.z;
        o.w = acc[u][3] + bv.w;
        *(float4*)&g_Wh[(size_t)(row0 + ty * 4 + u) * FOUT + tx * 4] = o;
        ps[u]  = o.x * a1.x + o.y * a1.y + o.z * a1.z + o.w * a1.w;
        pt2[u] = o.x * a2.x + o.y * a2.y + o.z * a2.z + o.w * a2.w;
    }
    // reduce across the 16 tx threads (lanes differ only in low 4 bits)
#pragma unroll
    for (int o = 8; o; o >>= 1) {
#pragma unroll
        for (int u = 0; u < 4; u++) {
            ps[u]  += __shfl_xor_sync(0xffffffffu, ps[u], o);
            pt2[u] += __shfl_xor_sync(0xffffffffu, pt2[u], o);
        }
    }
    if (tx == 0) {
        float abv = ab[0];
#pragma unroll
        for (int u = 0; u < 4; u++) {
            int row = row0 + ty * 4 + u;
            float sb = ps[u] + abv;
            float star = pt2[u];
            g_t[row]  = star;
            g_th[row] = -sb;
            g_P[row]  = expf(sb);
            g_p[row]  = expf(NEG * sb);
            g_E[row]  = expf(star);
            g_e[row]  = expf(NEG * star);
        }
    }
}

// ---- K2 (fused): blocks [0,SBLK) stream A for the denominator;
//                  blocks [SBLK,SBLK+RBLK) compute ranks + lower bounds ----
__global__ __launch_bounds__(256) void k2_rank_denom(const int* __restrict__ A) {
    __shared__ __align__(16) float st[GN];      // ranking blocks
    __shared__ float s1[16][8], s2[16][8];      // streaming blocks
    int bid = blockIdx.x;
    int tid = threadIdx.x;
    int lane = tid & 31, w = tid >> 5;

    if (bid < SBLK) {
        // ---------------- denominator: streams A (268 MB, DRAM-bound) ----------------
        int ib = bid * 16;
        float th[16];
        float acc1[16] = {}, acc2[16] = {};
#pragma unroll
        for (int r = 0; r < 16; r++) th[r] = g_th[ib + r];
#pragma unroll 1
        for (int it = 0; it < 8; it++) {
            int jq = it * 256 + tid;                 // quad index: cols 4*jq..4*jq+3
            float4 Ev = ((const float4*)g_E)[jq];
            float4 ev = ((const float4*)g_e)[jq];
            float4 tv = ((const float4*)g_t)[jq];
#pragma unroll
            for (int r = 0; r < 16; r++) {
                int4 a = __ldcs(((const int4*)A) + (size_t)(ib + r) * (GN / 4) + jq);
                if (a.x) { if (tv.x >= th[r]) acc1[r] += Ev.x; else acc2[r] += ev.x; }
                if (a.y) { if (tv.y >= th[r]) acc1[r] += Ev.y; else acc2[r] += ev.y; }
                if (a.z) { if (tv.z >= th[r]) acc1[r] += Ev.z; else acc2[r] += ev.z; }
                if (a.w) { if (tv.w >= th[r]) acc1[r] += Ev.w; else acc2[r] += ev.w; }
            }
        }
#pragma unroll
        for (int r = 0; r < 16; r++) {
            float v1 = acc1[r], v2 = acc2[r];
#pragma unroll
            for (int o = 16; o; o >>= 1) {
                v1 += __shfl_xor_sync(0xffffffffu, v1, o);
                v2 += __shfl_xor_sync(0xffffffffu, v2, o);
            }
            if (lane == 0) { s1[r][w] = v1; s2[r][w] = v2; }
        }
        __syncthreads();
        if (tid < 16) {
            float d1 = 0.f, d2 = 0.f;
#pragma unroll
            for (int q = 0; q < 8; q++) { d1 += s1[tid][q]; d2 += s2[tid][q]; }
            int i = ib + tid;
            g_denom[i] = g_P[i] * d1 + g_p[i] * d2;
        }
    } else {
        // ---------------- ranking: rank(t_i) + lower_bound(th_i), 8 queries/warp ----------------
        int rb = bid - SBLK;
        for (int i = tid; i < GN / 4; i += 256)
            ((float4*)st)[i] = ((const float4*)g_t)[i];
        __syncthreads();
        int   row[8];
        float qt[8], qth[8];
#pragma unroll
        for (int q = 0; q < 8; q++) {
            row[q] = rb * 64 + w * 8 + q;
            qt[q]  = g_t[row[q]];
            qth[q] = g_th[row[q]];
        }
        int cR[8] = {}, cK[8] = {};
#pragma unroll 2
        for (int i = 0; i < 64; i++) {
            float4 v = ((float4*)st)[i * 32 + lane];
            int m = (i * 32 + lane) * 4;
#pragma unroll
            for (int q = 0; q < 8; q++) {
                cR[q] += (v.x < qt[q]) + (v.x == qt[q] && (m + 0) < row[q]);
                cR[q] += (v.y < qt[q]) + (v.y == qt[q] && (m + 1) < row[q]);
                cR[q] += (v.z < qt[q]) + (v.z == qt[q] && (m + 2) < row[q]);
                cR[q] += (v.w < qt[q]) + (v.w == qt[q] && (m + 3) < row[q]);
                cK[q] += (v.x < qth[q]) + (v.y < qth[q]) + (v.z < qth[q]) + (v.w < qth[q]);
            }
        }
#pragma unroll
        for (int q = 0; q < 8; q++) {
#pragma unroll
            for (int o = 16; o; o >>= 1) {
                cR[q] += __shfl_xor_sync(0xffffffffu, cR[q], o);
                cK[q] += __shfl_xor_sync(0xffffffffu, cK[q], o);
            }
        }
        if (lane == 0) {
#pragma unroll
            for (int q = 0; q < 8; q++) {
                g_pos[cR[q]] = row[q];   // ranks form a permutation (tie-broken by index)
                g_k[row[q]]  = cK[q];
            }
        }
    }
}

// ---------------- K3: per-chunk weighted partial sums (128 chunks x 64) ----------------
__global__ __launch_bounds__(64) void k3_chunks() {
    int c = blockIdx.x, f = threadIdx.x;
    __shared__ int   sj[CSZ];
    __shared__ float swl[CSZ], swh[CSZ];
    {
        int jj = g_pos[c * CSZ + f];
        sj[f] = jj; swl[f] = g_e[jj]; swh[f] = g_E[jj];
    }
    __syncthreads();
    float accLo = 0.f, accHi = 0.f;
#pragma unroll 8
    for (int r = 0; r < CSZ; r++) {
        float x = g_Wh[(size_t)sj[r] * FOUT + f];
        accLo += swl[r] * x;
        accHi += swh[r] * x;
    }
    g_chunkLo[c * FOUT + f] = accLo;
    g_chunkHi[c * FOUT + f] = accHi;
}

// ---------------- K4: fill PreLo / SufHi (each block scans chunk sums itself) ----------------
__global__ __launch_bounds__(64) void k4_fill() {
    int c = blockIdx.x, f = threadIdx.x;
    __shared__ int   sj[CSZ];
    __shared__ float swl[CSZ], swh[CSZ];
    {
        int jj = g_pos[c * CSZ + f];
        sj[f] = jj; swl[f] = g_e[jj]; swh[f] = g_E[jj];
    }
    __syncthreads();
    float run = 0.f, run2 = 0.f;
    for (int cc = 0; cc < c; cc++)          run  += g_chunkLo[cc * FOUT + f];
    for (int cc = c + 1; cc < NCHUNK; cc++) run2 += g_chunkHi[cc * FOUT + f];

    int base = c * CSZ;
    // forward: exclusive prefix of e_j * Wh in sorted order
    for (int r0 = 0; r0 < CSZ; r0 += 8) {
        float x[8];
#pragma unroll
        for (int u = 0; u < 8; u++) x[u] = g_Wh[(size_t)sj[r0 + u] * FOUT + f];
#pragma unroll
        for (int u = 0; u < 8; u++) {
            g_PreLo[(size_t)(base + r0 + u) * FOUT + f] = run;
            run += swl[r0 + u] * x[u];
        }
    }
    if (c == NCHUNK - 1) g_PreLo[(size_t)GN * FOUT + f] = run;
    // backward: inclusive suffix of E_j * Wh in sorted order
    if (c == NCHUNK - 1) g_SufHi[(size_t)GN * FOUT + f] = 0.f;
    for (int r0 = CSZ - 8; r0 >= 0; r0 -= 8) {
        float x[8];
#pragma unroll
        for (int u = 0; u < 8; u++) x[u] = g_Wh[(size_t)sj[r0 + u] * FOUT + f];
#pragma unroll
        for (int u = 7; u >= 0; u--) {
            run2 += swh[r0 + u] * x[u];
            g_SufHi[(size_t)(base + r0 + u) * FOUT + f] = run2;
        }
    }
}

// ---------------- K5: gather + sigmoid ----------------
__global__ __launch_bounds__(256) void k5_out(float* __restrict__ out) {
    int gid = blockIdx.x * 256 + threadIdx.x;
    int i = gid >> 6, f = gid & 63;
    int k = g_k[i];
    float num = g_P[i] * g_SufHi[(size_t)k * FOUT + f] +
                g_p[i] * g_PreLo[(size_t)k * FOUT + f];
    float z = num / g_denom[i];
    out[gid] = 1.0f / (1.0f + __expf(-z));
}

// ---------------- launch ----------------
extern "C" void kernel_launch(void* const* d_in, const int* in_sizes, int n_in,
                              void* d_out, int out_size) {
    const float* H  = (const float*)d_in[0];
    const int*   A  = (const int*)d_in[1];
    const float* W  = (const float*)d_in[2];
    const float* bW = (const float*)d_in[3];
    const float* aw = (const float*)d_in[4];
    const float* ab = (const float*)d_in[5];
    float* out = (float*)d_out;

    k1_gemm_scal<<<GN / 64, 256>>>(H, W, bW, aw, ab);
    k2_rank_denom<<<SBLK + RBLK, 256>>>(A);
    k3_chunks<<<NCHUNK, 64>>>();
    k4_fill<<<NCHUNK, 64>>>();
    k5_out<<<(GN * FOUT) / 256, 256>>>(out);
}

// round 4
// speedup vs baseline: 1.4585x; 1.2953x over previous
#include <cuda_runtime.h>
#include <math.h>

#define GN     8192
#define FIN    256
#define FOUT   64
#define NEG    0.01f
#define RBLK   256      // ranking blocks (scheduled FIRST)
#define SROWS  8        // rows per streaming block
#define SBLK   (GN / SROWS)
#define NCHUNK 512      // sorted-order chunks
#define CSZ    16       // elements per chunk

// ---------------- device scratch ----------------
__device__ __align__(16) float g_Wh[GN * FOUT];
__device__ __align__(16) float    g_t[GN];    // s_tar
__device__ __align__(16) float    g_th[GN];   // -(s_src + a_b)
__device__ __align__(16) unsigned g_su[GN];   // sortable(t)
__device__ __align__(16) unsigned g_sth[GN];  // sortable(th)
__device__ __align__(16) float    g_P[GN];    // exp(s_src + a_b)
__device__ __align__(16) float    g_p[GN];    // exp(0.01*(s_src+a_b))
__device__ __align__(16) float    g_E[GN];    // exp(t)
__device__ __align__(16) float    g_e[GN];    // exp(0.01*t)
__device__ __align__(16) int      g_pos[GN];  // sorted pos -> original idx
__device__ __align__(16) int      g_k[GN];    // lower_bound(t_sorted, th_i)
__device__ __align__(16) float    g_cLo[NCHUNK * FOUT];
__device__ __align__(16) float    g_cHi[NCHUNK * FOUT];
__device__ __align__(16) float    g_Pre[NCHUNK * FOUT];          // exclusive prefix of cLo
__device__ __align__(16) float    g_Suf[(NCHUNK + 1) * FOUT];    // suffix sum of cHi
__device__ __align__(16) float    g_denom[GN];

__device__ __forceinline__ unsigned sortable(float f) {
    unsigned u = __float_as_uint(f);
    return (u & 0x80000000u) ? ~u : (u | 0x80000000u);
}

// ---------------- K1: Wh = H @ W + bW  + per-row scalar epilogue ----------------
__global__ __launch_bounds__(256) void k1_gemm_scal(const float* __restrict__ H,
                                                    const float* __restrict__ W,
                                                    const float* __restrict__ bW,
                                                    const float* __restrict__ aw,
                                                    const float* __restrict__ ab) {
    __shared__ float Hs[32][64];
    __shared__ float Ws[32][64];
    int tid = threadIdx.x;
    int row0 = blockIdx.x * 64;
    int tx = tid & 15, ty = tid >> 4;
    float acc[4][4] = {};
    for (int k0 = 0; k0 < FIN; k0 += 32) {
#pragma unroll
        for (int i = 0; i < 2; i++) {
            int idx = tid + i * 256;
            int r = idx >> 3, kq = idx & 7;
            float4 v = *(const float4*)(H + (size_t)(row0 + r) * FIN + k0 + kq * 4);
            Hs[kq * 4 + 0][r] = v.x;
            Hs[kq * 4 + 1][r] = v.y;
            Hs[kq * 4 + 2][r] = v.z;
            Hs[kq * 4 + 3][r] = v.w;
        }
#pragma unroll
        for (int i = 0; i < 2; i++) {
            int idx = tid + i * 256;
            int kk = idx >> 4, cq = idx & 15;
            *(float4*)&Ws[kk][cq * 4] =
                *(const float4*)(W + (size_t)(k0 + kk) * FOUT + cq * 4);
        }
        __syncthreads();
#pragma unroll
        for (int kk = 0; kk < 32; kk++) {
            float4 a = *(float4*)&Hs[kk][ty * 4];
            float4 b = *(float4*)&Ws[kk][tx * 4];
            acc[0][0] += a.x * b.x; acc[0][1] += a.x * b.y; acc[0][2] += a.x * b.z; acc[0][3] += a.x * b.w;
            acc[1][0] += a.y * b.x; acc[1][1] += a.y * b.y; acc[1][2] += a.y * b.z; acc[1][3] += a.y * b.w;
            acc[2][0] += a.z * b.x; acc[2][1] += a.z * b.y; acc[2][2] += a.z * b.z; acc[2][3] += a.z * b.w;
            acc[3][0] += a.w * b.x; acc[3][1] += a.w * b.y; acc[3][2] += a.w * b.z; acc[3][3] += a.w * b.w;
        }
        __syncthreads();
    }
    float4 bv = *(const float4*)(bW + tx * 4);
    float4 a1 = *(const float4*)(aw + tx * 4);
    float4 a2 = *(const float4*)(aw + FOUT + tx * 4);
    float ps[4], pt2[4];
#pragma unroll
    for (int u = 0; u < 4; u++) {
        float4 o;
        o.x = acc[u][0] + bv.x;
        o.y = acc[u][1] + bv.y;
        o.z = acc[u][2] + bv.z;
        o.w = acc[u][3] + bv.w;
        *(float4*)&g_Wh[(size_t)(row0 + ty * 4 + u) * FOUT + tx * 4] = o;
        ps[u]  = o.x * a1.x + o.y * a1.y + o.z * a1.z + o.w * a1.w;
        pt2[u] = o.x * a2.x + o.y * a2.y + o.z * a2.z + o.w * a2.w;
    }
#pragma unroll
    for (int o = 8; o; o >>= 1) {
#pragma unroll
        for (int u = 0; u < 4; u++) {
            ps[u]  += __shfl_xor_sync(0xffffffffu, ps[u], o);
            pt2[u] += __shfl_xor_sync(0xffffffffu, pt2[u], o);
        }
    }
    if (tx == 0) {
        float abv = ab[0];
#pragma unroll
        for (int u = 0; u < 4; u++) {
            int row = row0 + ty * 4 + u;
            float sb = ps[u] + abv;
            float star = pt2[u];
            float thv = -sb;
            g_t[row]   = star;
            g_th[row]  = thv;
            g_su[row]  = sortable(star);
            g_sth[row] = sortable(thv);
            g_P[row]   = expf(sb);
            g_p[row]   = expf(NEG * sb);
            g_E[row]   = expf(star);
            g_e[row]   = expf(NEG * star);
        }
    }
}

// ---- K2 (fused): blocks [0,RBLK) rank; blocks [RBLK, RBLK+SBLK) stream A ----
__global__ __launch_bounds__(256) void k2_rank_denom(const int* __restrict__ A) {
    __shared__ __align__(16) unsigned su[GN];   // 32 KB (ranking)
    __shared__ float s1[SROWS][8], s2[SROWS][8];
    int bid = blockIdx.x;
    int tid = threadIdx.x;
    int lane = tid & 31, w = tid >> 5;

    if (bid < RBLK) {
        // ---------------- ranking: 4 queries per warp, sortable-uint compares ----------------
        for (int i = tid; i < GN / 4; i += 256)
            ((uint4*)su)[i] = ((const uint4*)g_su)[i];
        __syncthreads();
        unsigned sq[4], sthv[4];
        int row[4];
#pragma unroll
        for (int q = 0; q < 4; q++) {
            row[q]  = bid * 32 + w * 4 + q;
            sq[q]   = g_su[row[q]];
            sthv[q] = g_sth[row[q]];
        }
        int cR[4] = {}, cK[4] = {};
#pragma unroll 2
        for (int i = 0; i < 64; i++) {
            uint4 v = ((uint4*)su)[i * 32 + lane];
            int m = (i * 32 + lane) * 4;
#pragma unroll
            for (int q = 0; q < 4; q++) {
                cR[q] += (v.x < sq[q]) + (v.x == sq[q] && (m + 0) < row[q]);
                cR[q] += (v.y < sq[q]) + (v.y == sq[q] && (m + 1) < row[q]);
                cR[q] += (v.z < sq[q]) + (v.z == sq[q] && (m + 2) < row[q]);
                cR[q] += (v.w < sq[q]) + (v.w == sq[q] && (m + 3) < row[q]);
                cK[q] += (v.x < sthv[q]) + (v.y < sthv[q]) + (v.z < sthv[q]) + (v.w < sthv[q]);
            }
        }
#pragma unroll
        for (int q = 0; q < 4; q++) {
#pragma unroll
            for (int o = 16; o; o >>= 1) {
                cR[q] += __shfl_xor_sync(0xffffffffu, cR[q], o);
                cK[q] += __shfl_xor_sync(0xffffffffu, cK[q], o);
            }
        }
        if (lane == 0) {
#pragma unroll
            for (int q = 0; q < 4; q++) {
                g_pos[cR[q]] = row[q];
                g_k[row[q]]  = cK[q];
            }
        }
    } else {
        // ---------------- denominator: streams A (268 MB, DRAM-bound) ----------------
        int ib = (bid - RBLK) * SROWS;
        float th[SROWS];
        float acc1[SROWS] = {}, acc2[SROWS] = {};
#pragma unroll
        for (int r = 0; r < SROWS; r++) th[r] = g_th[ib + r];
#pragma unroll 1
        for (int it = 0; it < 8; it++) {
            int jq = it * 256 + tid;
            float4 Ev = ((const float4*)g_E)[jq];
            float4 ev = ((const float4*)g_e)[jq];
            float4 tv = ((const float4*)g_t)[jq];
#pragma unroll
            for (int r = 0; r < SROWS; r++) {
                int4 a = __ldcs(((const int4*)A) + (size_t)(ib + r) * (GN / 4) + jq);
                if (a.x) { if (tv.x >= th[r]) acc1[r] += Ev.x; else acc2[r] += ev.x; }
                if (a.y) { if (tv.y >= th[r]) acc1[r] += Ev.y; else acc2[r] += ev.y; }
                if (a.z) { if (tv.z >= th[r]) acc1[r] += Ev.z; else acc2[r] += ev.z; }
                if (a.w) { if (tv.w >= th[r]) acc1[r] += Ev.w; else acc2[r] += ev.w; }
            }
        }
#pragma unroll
        for (int r = 0; r < SROWS; r++) {
            float v1 = acc1[r], v2 = acc2[r];
#pragma unroll
            for (int o = 16; o; o >>= 1) {
                v1 += __shfl_xor_sync(0xffffffffu, v1, o);
                v2 += __shfl_xor_sync(0xffffffffu, v2, o);
            }
            if (lane == 0) { s1[r][w] = v1; s2[r][w] = v2; }
        }
        __syncthreads();
        if (tid < SROWS) {
            float d1 = 0.f, d2 = 0.f;
#pragma unroll
            for (int q = 0; q < 8; q++) { d1 += s1[tid][q]; d2 += s2[tid][q]; }
            int i = ib + tid;
            g_denom[i] = g_P[i] * d1 + g_p[i] * d2;
        }
    }
}

// ---------------- K3: per-chunk weighted sums (512 chunks x 16) ----------------
__global__ __launch_bounds__(256) void k3_chunks() {
    int c = blockIdx.x, tid = threadIdx.x;
    __shared__ int   sj[CSZ];
    __shared__ float swl[CSZ], swh[CSZ];
    __shared__ float sLo[4][FOUT], sHi[4][FOUT];
    if (tid < CSZ) {
        int jj = g_pos[c * CSZ + tid];
        sj[tid] = jj; swl[tid] = g_e[jj]; swh[tid] = g_E[jj];
    }
    __syncthreads();
    int rq = tid >> 6, f = tid & 63;
    float lo = 0.f, hi = 0.f;
#pragma unroll
    for (int u = 0; u < 4; u++) {
        int r = rq * 4 + u;
        float x = g_Wh[(size_t)sj[r] * FOUT + f];
        lo += swl[r] * x;
        hi += swh[r] * x;
    }
    sLo[rq][f] = lo; sHi[rq][f] = hi;
    __syncthreads();
    if (tid < FOUT) {
        float l = sLo[0][tid] + sLo[1][tid] + sLo[2][tid] + sLo[3][tid];
        float h = sHi[0][tid] + sHi[1][tid] + sHi[2][tid] + sHi[3][tid];
        g_cLo[c * FOUT + tid] = l;
        g_cHi[c * FOUT + tid] = h;
    }
}

// ---------------- K4: block-parallel scans over chunks (per f) ----------------
__global__ __launch_bounds__(NCHUNK) void k4_scan() {
    int f = blockIdx.x, c = threadIdx.x;
    __shared__ float sa[NCHUNK];
    // exclusive prefix of cLo
    sa[c] = g_cLo[c * FOUT + f];
    __syncthreads();
    for (int off = 1; off < NCHUNK; off <<= 1) {
        float add = (c >= off) ? sa[c - off] : 0.f;
        __syncthreads();
        sa[c] += add;
        __syncthreads();
    }
    g_Pre[c * FOUT + f] = (c > 0) ? sa[c - 1] : 0.f;
    __syncthreads();
    // suffix (inclusive) of cHi: scan reversed
    sa[NCHUNK - 1 - c] = g_cHi[c * FOUT + f];
    __syncthreads();
    for (int off = 1; off < NCHUNK; off <<= 1) {
        float add = (c >= off) ? sa[c - off] : 0.f;
        __syncthreads();
        sa[c] += add;
        __syncthreads();
    }
    g_Suf[c * FOUT + f] = sa[NCHUNK - 1 - c];
    if (c == 0) g_Suf[(size_t)NCHUNK * FOUT + f] = 0.f;
}

// ---------------- K5: direct output (4 queries per block) ----------------
__global__ __launch_bounds__(256) void k5_out(float* __restrict__ out) {
    int tid = threadIdx.x;
    __shared__ int   sj[4][CSZ];
    __shared__ float sl[4][CSZ], sh[4][CSZ];
    if (tid < 64) {
        int q = tid >> 4, r = tid & 15;
        int iq = blockIdx.x * 4 + q;
        int kq = g_k[iq];
        int cq = min(kq >> 4, NCHUNK - 1);
        int jj = g_pos[cq * CSZ + r];
        sj[q][r] = jj; sl[q][r] = g_e[jj]; sh[q][r] = g_E[jj];
    }
    __syncthreads();
    int q = tid >> 6, f = tid & 63;
    int i = blockIdx.x * 4 + q;
    int k = g_k[i];
    int c = min(k >> 4, NCHUNK - 1);
    int o = k - (c << 4);
    float x[CSZ];
#pragma unroll
    for (int r = 0; r < CSZ; r++)
        x[r] = g_Wh[(size_t)sj[q][r] * FOUT + f];
    float lo = 0.f, hi = 0.f;
#pragma unroll
    for (int r = 0; r < CSZ; r++) {
        if (r < o) lo += sl[q][r] * x[r];
        else       hi += sh[q][r] * x[r];
    }
    float lo_t = g_Pre[c * FOUT + f] + lo;
    float hi_t = g_Suf[(c + 1) * FOUT + f] + hi;
    float num = g_P[i] * hi_t + g_p[i] * lo_t;
    float z = num / g_denom[i];
    out[(size_t)i * FOUT + f] = 1.0f / (1.0f + __expf(-z));
}

// ---------------- launch ----------------
extern "C" void kernel_launch(void* const* d_in, const int* in_sizes, int n_in,
                              void* d_out, int out_size) {
    const float* H  = (const float*)d_in[0];
    const int*   A  = (const int*)d_in[1];
    const float* W  = (const float*)d_in[2];
    const float* bW = (const float*)d_in[3];
    const float* aw = (const float*)d_in[4];
    const float* ab = (const float*)d_in[5];
    float* out = (float*)d_out;

    k1_gemm_scal<<<GN / 64, 256>>>(H, W, bW, aw, ab);
    k2_rank_denom<<<RBLK + SBLK, 256>>>(A);
    k3_chunks<<<NCHUNK, 256>>>();
    k4_scan<<<FOUT, NCHUNK>>>();
    k5_out<<<GN / 4, 256>>>(out);
}

// round 5
// speedup vs baseline: 1.8585x; 1.2743x over previous
#include <cuda_runtime.h>
#include <math.h>

#define GN     8192
#define FIN    256
#define FOUT   64
#define NEG    0.01f
#define RBLK   256      // ranking blocks (scheduled FIRST)
#define SROWS  8        // rows per streaming block
#define SBLK   (GN / SROWS)
#define NCHUNK 512      // sorted-order chunks
#define CSZ    16       // elements per chunk

// ---------------- device scratch ----------------
__device__ __align__(16) float g_Wh[GN * FOUT];
__device__ __align__(16) float    g_t[GN];    // s_tar
__device__ __align__(16) float    g_th[GN];   // -(s_src + a_b)
__device__ __align__(16) unsigned g_su[GN];   // sortable(t)
__device__ __align__(16) unsigned g_sth[GN];  // sortable(th)
__device__ __align__(16) float    g_P[GN];    // exp(s_src + a_b)
__device__ __align__(16) float    g_p[GN];    // exp(0.01*(s_src+a_b))
__device__ __align__(16) float    g_E[GN];    // exp(t)
__device__ __align__(16) float    g_e[GN];    // exp(0.01*t)
__device__ __align__(16) int      g_pos[GN];  // sorted pos -> original idx
__device__ __align__(16) int      g_k[GN];    // lower_bound(t_sorted, th_i)
__device__ __align__(16) float    g_cLoT[FOUT * NCHUNK];  // transposed [f][c]
__device__ __align__(16) float    g_cHiT[FOUT * NCHUNK];  // transposed [f][c]
__device__ __align__(16) float    g_Pre[NCHUNK * FOUT];        // exclusive prefix of cLo, [c][f]
__device__ __align__(16) float    g_Suf[(NCHUNK + 1) * FOUT];  // inclusive suffix of cHi, [c][f]
__device__ __align__(16) float    g_denom[GN];

__device__ __forceinline__ unsigned sortable(float f) {
    unsigned u = __float_as_uint(f);
    return (u & 0x80000000u) ? ~u : (u | 0x80000000u);
}

// ---------------- K1: Wh = H @ W + bW  + per-row scalar epilogue ----------------
__global__ __launch_bounds__(256) void k1_gemm_scal(const float* __restrict__ H,
                                                    const float* __restrict__ W,
                                                    const float* __restrict__ bW,
                                                    const float* __restrict__ aw,
                                                    const float* __restrict__ ab) {
    __shared__ float Hs[32][64];
    __shared__ float Ws[32][64];
    int tid = threadIdx.x;
    int row0 = blockIdx.x * 64;
    int tx = tid & 15, ty = tid >> 4;
    float acc[4][4] = {};
    for (int k0 = 0; k0 < FIN; k0 += 32) {
#pragma unroll
        for (int i = 0; i < 2; i++) {
            int idx = tid + i * 256;
            int r = idx >> 3, kq = idx & 7;
            float4 v = *(const float4*)(H + (size_t)(row0 + r) * FIN + k0 + kq * 4);
            Hs[kq * 4 + 0][r] = v.x;
            Hs[kq * 4 + 1][r] = v.y;
            Hs[kq * 4 + 2][r] = v.z;
            Hs[kq * 4 + 3][r] = v.w;
        }
#pragma unroll
        for (int i = 0; i < 2; i++) {
            int idx = tid + i * 256;
            int kk = idx >> 4, cq = idx & 15;
            *(float4*)&Ws[kk][cq * 4] =
                *(const float4*)(W + (size_t)(k0 + kk) * FOUT + cq * 4);
        }
        __syncthreads();
#pragma unroll
        for (int kk = 0; kk < 32; kk++) {
            float4 a = *(float4*)&Hs[kk][ty * 4];
            float4 b = *(float4*)&Ws[kk][tx * 4];
            acc[0][0] += a.x * b.x; acc[0][1] += a.x * b.y; acc[0][2] += a.x * b.z; acc[0][3] += a.x * b.w;
            acc[1][0] += a.y * b.x; acc[1][1] += a.y * b.y; acc[1][2] += a.y * b.z; acc[1][3] += a.y * b.w;
            acc[2][0] += a.z * b.x; acc[2][1] += a.z * b.y; acc[2][2] += a.z * b.z; acc[2][3] += a.z * b.w;
            acc[3][0] += a.w * b.x; acc[3][1] += a.w * b.y; acc[3][2] += a.w * b.z; acc[3][3] += a.w * b.w;
        }
        __syncthreads();
    }
    float4 bv = *(const float4*)(bW + tx * 4);
    float4 a1 = *(const float4*)(aw + tx * 4);
    float4 a2 = *(const float4*)(aw + FOUT + tx * 4);
    float ps[4], pt2[4];
#pragma unroll
    for (int u = 0; u < 4; u++) {
        float4 o;
        o.x = acc[u][0] + bv.x;
        o.y = acc[u][1] + bv.y;
        o.z = acc[u][2] + bv.z;
        o.w = acc[u][3] + bv.w;
        *(float4*)&g_Wh[(size_t)(row0 + ty * 4 + u) * FOUT + tx * 4] = o;
        ps[u]  = o.x * a1.x + o.y * a1.y + o.z * a1.z + o.w * a1.w;
        pt2[u] = o.x * a2.x + o.y * a2.y + o.z * a2.z + o.w * a2.w;
    }
#pragma unroll
    for (int o = 8; o; o >>= 1) {
#pragma unroll
        for (int u = 0; u < 4; u++) {
            ps[u]  += __shfl_xor_sync(0xffffffffu, ps[u], o);
            pt2[u] += __shfl_xor_sync(0xffffffffu, pt2[u], o);
        }
    }
    if (tx == 0) {
        float abv = ab[0];
#pragma unroll
        for (int u = 0; u < 4; u++) {
            int row = row0 + ty * 4 + u;
            float sb = ps[u] + abv;
            float star = pt2[u];
            float thv = -sb;
            g_t[row]   = star;
            g_th[row]  = thv;
            g_su[row]  = sortable(star);
            g_sth[row] = sortable(thv);
            g_P[row]   = expf(sb);
            g_p[row]   = expf(NEG * sb);
            g_E[row]   = expf(star);
            g_e[row]   = expf(NEG * star);
        }
    }
}

// ---------------- dummy (profiling-position shim) ----------------
__global__ void kdummy() {}

// ---- K2 (fused): blocks [0,RBLK) rank; blocks [RBLK, RBLK+SBLK) stream A ----
__global__ __launch_bounds__(256) void k2_rank_denom(const int* __restrict__ A) {
    __shared__ __align__(16) unsigned su[GN];   // 32 KB (ranking)
    __shared__ float s1[SROWS][8], s2[SROWS][8];
    int bid = blockIdx.x;
    int tid = threadIdx.x;
    int lane = tid & 31, w = tid >> 5;

    if (bid < RBLK) {
        // ---------------- ranking: 4 queries per warp, sortable-uint compares ----------------
        for (int i = tid; i < GN / 4; i += 256)
            ((uint4*)su)[i] = ((const uint4*)g_su)[i];
        __syncthreads();
        unsigned sq[4], sthv[4];
        int row[4];
#pragma unroll
        for (int q = 0; q < 4; q++) {
            row[q]  = bid * 32 + w * 4 + q;
            sq[q]   = g_su[row[q]];
            sthv[q] = g_sth[row[q]];
        }
        int cR[4] = {}, cK[4] = {};
#pragma unroll 2
        for (int i = 0; i < 64; i++) {
            uint4 v = ((uint4*)su)[i * 32 + lane];
            int m = (i * 32 + lane) * 4;
#pragma unroll
            for (int q = 0; q < 4; q++) {
                cR[q] += (v.x < sq[q]) + (v.x == sq[q] && (m + 0) < row[q]);
                cR[q] += (v.y < sq[q]) + (v.y == sq[q] && (m + 1) < row[q]);
                cR[q] += (v.z < sq[q]) + (v.z == sq[q] && (m + 2) < row[q]);
                cR[q] += (v.w < sq[q]) + (v.w == sq[q] && (m + 3) < row[q]);
                cK[q] += (v.x < sthv[q]) + (v.y < sthv[q]) + (v.z < sthv[q]) + (v.w < sthv[q]);
            }
        }
#pragma unroll
        for (int q = 0; q < 4; q++) {
#pragma unroll
            for (int o = 16; o; o >>= 1) {
                cR[q] += __shfl_xor_sync(0xffffffffu, cR[q], o);
                cK[q] += __shfl_xor_sync(0xffffffffu, cK[q], o);
            }
        }
        if (lane == 0) {
#pragma unroll
            for (int q = 0; q < 4; q++) {
                g_pos[cR[q]] = row[q];
                g_k[row[q]]  = cK[q];
            }
        }
    } else {
        // ---------------- denominator: streams A (268 MB, DRAM-bound) ----------------
        int ib = (bid - RBLK) * SROWS;
        float th[SROWS];
        float acc1[SROWS] = {}, acc2[SROWS] = {};
#pragma unroll
        for (int r = 0; r < SROWS; r++) th[r] = g_th[ib + r];
#pragma unroll 1
        for (int it = 0; it < 8; it++) {
            int jq = it * 256 + tid;
            float4 Ev = ((const float4*)g_E)[jq];
            float4 ev = ((const float4*)g_e)[jq];
            float4 tv = ((const float4*)g_t)[jq];
            int4 a[SROWS];
#pragma unroll
            for (int r = 0; r < SROWS; r++)
                a[r] = __ldcs(((const int4*)A) + (size_t)(ib + r) * (GN / 4) + jq);
#pragma unroll
            for (int r = 0; r < SROWS; r++) {
                float thr = th[r];
                if (a[r].x) { if (tv.x >= thr) acc1[r] += Ev.x; else acc2[r] += ev.x; }
                if (a[r].y) { if (tv.y >= thr) acc1[r] += Ev.y; else acc2[r] += ev.y; }
                if (a[r].z) { if (tv.z >= thr) acc1[r] += Ev.z; else acc2[r] += ev.z; }
                if (a[r].w) { if (tv.w >= thr) acc1[r] += Ev.w; else acc2[r] += ev.w; }
            }
        }
#pragma unroll
        for (int r = 0; r < SROWS; r++) {
            float v1 = acc1[r], v2 = acc2[r];
#pragma unroll
            for (int o = 16; o; o >>= 1) {
                v1 += __shfl_xor_sync(0xffffffffu, v1, o);
                v2 += __shfl_xor_sync(0xffffffffu, v2, o);
            }
            if (lane == 0) { s1[r][w] = v1; s2[r][w] = v2; }
        }
        __syncthreads();
        if (tid < SROWS) {
            float d1 = 0.f, d2 = 0.f;
#pragma unroll
            for (int q = 0; q < 8; q++) { d1 += s1[tid][q]; d2 += s2[tid][q]; }
            int i = ib + tid;
            g_denom[i] = g_P[i] * d1 + g_p[i] * d2;
        }
    }
}

// ---------------- K3: per-chunk weighted sums (512 chunks x 16), transposed out ----------------
__global__ __launch_bounds__(256) void k3_chunks() {
    int c = blockIdx.x, tid = threadIdx.x;
    __shared__ int   sj[CSZ];
    __shared__ float swl[CSZ], swh[CSZ];
    __shared__ float sLo[4][FOUT], sHi[4][FOUT];
    if (tid < CSZ) {
        int jj = g_pos[c * CSZ + tid];
        sj[tid] = jj; swl[tid] = g_e[jj]; swh[tid] = g_E[jj];
    }
    __syncthreads();
    int rq = tid >> 6, f = tid & 63;
    float lo = 0.f, hi = 0.f;
#pragma unroll
    for (int u = 0; u < 4; u++) {
        int r = rq * 4 + u;
        float x = g_Wh[(size_t)sj[r] * FOUT + f];
        lo += swl[r] * x;
        hi += swh[r] * x;
    }
    sLo[rq][f] = lo; sHi[rq][f] = hi;
    __syncthreads();
    if (tid < FOUT) {
        float l = sLo[0][tid] + sLo[1][tid] + sLo[2][tid] + sLo[3][tid];
        float h = sHi[0][tid] + sHi[1][tid] + sHi[2][tid] + sHi[3][tid];
        g_cLoT[(size_t)tid * NCHUNK + c] = l;
        g_cHiT[(size_t)tid * NCHUNK + c] = h;
    }
}

// ---------------- K4: warp-per-feature register scan over 512 chunks ----------------
__global__ __launch_bounds__(256) void k4_scan() {
    int wf = threadIdx.x >> 5;
    int lane = threadIdx.x & 31;
    int f = blockIdx.x * 8 + wf;
    // ---- Pre: exclusive prefix of cLo over chunks ----
    {
        const float* src = g_cLoT + (size_t)f * NCHUNK + lane * 16;
        float v[16];
#pragma unroll
        for (int u = 0; u < 16; u += 4) {
            float4 q = *(const float4*)(src + u);
            v[u] = q.x; v[u + 1] = q.y; v[u + 2] = q.z; v[u + 3] = q.w;
        }
        float run = 0.f, inc[16];
#pragma unroll
        for (int u = 0; u < 16; u++) { run += v[u]; inc[u] = run; }
        float tot = run, scan = run;
#pragma unroll
        for (int o = 1; o < 32; o <<= 1) {
            float n = __shfl_up_sync(0xffffffffu, scan, o);
            if (lane >= o) scan += n;
        }
        float off = scan - tot;
#pragma unroll
        for (int u = 0; u < 16; u++)
            g_Pre[(size_t)(lane * 16 + u) * FOUT + f] = off + (inc[u] - v[u]);
    }
    // ---- Suf: inclusive suffix of cHi = total - exclusive prefix ----
    {
        const float* src = g_cHiT + (size_t)f * NCHUNK + lane * 16;
        float v[16];
#pragma unroll
        for (int u = 0; u < 16; u += 4) {
            float4 q = *(const float4*)(src + u);
            v[u] = q.x; v[u + 1] = q.y; v[u + 2] = q.z; v[u + 3] = q.w;
        }
        float run = 0.f, inc[16];
#pragma unroll
        for (int u = 0; u < 16; u++) { run += v[u]; inc[u] = run; }
        float tot = run, scan = run;
#pragma unroll
        for (int o = 1; o < 32; o <<= 1) {
            float n = __shfl_up_sync(0xffffffffu, scan, o);
            if (lane >= o) scan += n;
        }
        float off = scan - tot;
        float total = __shfl_sync(0xffffffffu, scan, 31);
#pragma unroll
        for (int u = 0; u < 16; u++)
            g_Suf[(size_t)(lane * 16 + u) * FOUT + f] = total - (off + (inc[u] - v[u]));
        if (lane == 31) g_Suf[(size_t)NCHUNK * FOUT + f] = 0.f;
    }
}

// ---------------- K5: direct output (4 queries per block) ----------------
__global__ __launch_bounds__(256) void k5_out(float* __restrict__ out) {
    int tid = threadIdx.x;
    __shared__ int   sj[4][CSZ];
    __shared__ float sl[4][CSZ], sh[4][CSZ];
    if (tid < 64) {
        int q = tid >> 4, r = tid & 15;
        int iq = blockIdx.x * 4 + q;
        int kq = g_k[iq];
        int cq = min(kq >> 4, NCHUNK - 1);
        int jj = g_pos[cq * CSZ + r];
        sj[q][r] = jj; sl[q][r] = g_e[jj]; sh[q][r] = g_E[jj];
    }
    __syncthreads();
    int q = tid >> 6, f = tid & 63;
    int i = blockIdx.x * 4 + q;
    int k = g_k[i];
    int c = min(k >> 4, NCHUNK - 1);
    int o = k - (c << 4);
    float x[CSZ];
#pragma unroll
    for (int r = 0; r < CSZ; r++)
        x[r] = g_Wh[(size_t)sj[q][r] * FOUT + f];
    float lo = 0.f, hi = 0.f;
#pragma unroll
    for (int r = 0; r < CSZ; r++) {
        if (r < o) lo += sl[q][r] * x[r];
        else       hi += sh[q][r] * x[r];
    }
    float lo_t = g_Pre[c * FOUT + f] + lo;
    float hi_t = g_Suf[(c + 1) * FOUT + f] + hi;
    float num = g_P[i] * hi_t + g_p[i] * lo_t;
    float z = num / g_denom[i];
    out[(size_t)i * FOUT + f] = 1.0f / (1.0f + __expf(-z));
}

// ---------------- launch ----------------
extern "C" void kernel_launch(void* const* d_in, const int* in_sizes, int n_in,
                              void* d_out, int out_size) {
    const float* H  = (const float*)d_in[0];
    const int*   A  = (const int*)d_in[1];
    const float* W  = (const float*)d_in[2];
    const float* bW = (const float*)d_in[3];
    const float* aw = (const float*)d_in[4];
    const float* ab = (const float*)d_in[5];
    float* out = (float*)d_out;

    k1_gemm_scal<<<GN / 64, 256>>>(H, W, bW, aw, ab);
    kdummy<<<1, 32>>>();                     // shim: puts k2 at profiled position 4
    kdummy<<<1, 32>>>();
    k2_rank_denom<<<RBLK + SBLK, 256>>>(A);
    k3_chunks<<<NCHUNK, 256>>>();
    k4_scan<<<FOUT / 8, 256>>>();
    k5_out<<<GN / 4, 256>>>(out);
}